// round 6
// baseline (speedup 1.0000x reference)
#include <cuda_runtime.h>
#include <cuda_bf16.h>
#include <cstdint>

// Problem constants (fixed shapes)
#define BATCH 2
#define CDIM 128
#define NPIX 65536          // 256*256
#define LAST0 64512         // (chunks-1)*M
#define NROWBLK 4096        // NPIX/16
#define SCALE_L2 20.6099075f   // 1/(0.07 * ln2)
#define LN2F 0.6931471805599453f

typedef unsigned long long u64;

// ---------------- scratch (device globals: no allocations allowed) ----------
__device__ uint4  g_Apack[BATCH * NROWBLK * 4 * 32];   // 16.8 MB int8 mma A fragments
__device__ uint4  g_Bpack[BATCH * 16 * 512];           // 256 KB int8 B fragments
__device__ float  g_ra[BATCH * NPIX];                  // row dequant scale
__device__ float  g_rb[BATCH * NPIX];                  // col dequant scale (incl SCALE_L2)
__device__ float  g_qb2[BATCH * NPIX];                 // z2 quant multiplier 127/max
__device__ float  g_posl2[BATCH * NPIX];               // pos logit in log2 domain (fp32)
__device__ double g_acc;

// ---------------- helpers ----------------
// pack 4 floats -> 4x int8 in a .b32 (byte0 = f0); |f| <= 127 guaranteed
__device__ __forceinline__ unsigned pk4i(float f0, float f1, float f2, float f3) {
    int i0 = __float2int_rn(f0), i1 = __float2int_rn(f1);
    int i2 = __float2int_rn(f2), i3 = __float2int_rn(f3);
    unsigned t01, t23, r;
    asm("prmt.b32 %0,%1,%2,0x0040;" : "=r"(t01) : "r"(i0), "r"(i1));
    asm("prmt.b32 %0,%1,%2,0x0040;" : "=r"(t23) : "r"(i2), "r"(i3));
    asm("prmt.b32 %0,%1,%2,0x5410;" : "=r"(r)   : "r"(t01), "r"(t23));
    return r;
}
__device__ __forceinline__ u64 pk(float lo, float hi) {
    u64 r; asm("mov.b64 %0,{%1,%2};" : "=l"(r) : "f"(lo), "f"(hi)); return r;
}
__device__ __forceinline__ u64 bc(float x) {
    u64 r; asm("mov.b64 %0,{%1,%1};" : "=l"(r) : "f"(x)); return r;
}
__device__ __forceinline__ u64 fma2(u64 a, u64 b, u64 c) {
    u64 d; asm("fma.rn.f32x2 %0,%1,%2,%3;" : "=l"(d) : "l"(a), "l"(b), "l"(c)); return d;
}
__device__ __forceinline__ u64 add2(u64 a, u64 b) {
    u64 d; asm("add.rn.f32x2 %0,%1,%2;" : "=l"(d) : "l"(a), "l"(b)); return d;
}
__device__ __forceinline__ u64 mul2(u64 a, u64 b) {
    u64 d; asm("mul.rn.f32x2 %0,%1,%2;" : "=l"(d) : "l"(a), "l"(b)); return d;
}
// scalar exp2 (pos only). Exact at x==0.
__device__ __forceinline__ float exp2p(float x) {
    int   i = __float2int_rn(x);
    float f = x - (float)i;
    float p = 1.3333558146e-3f;
    p = fmaf(p, f, 9.6181291076e-3f);
    p = fmaf(p, f, 5.5504108664e-2f);
    p = fmaf(p, f, 2.4022650696e-1f);
    p = fmaf(p, f, 6.9314718056e-1f);
    p = fmaf(p, f, 1.0f);
    return __int_as_float(__float_as_int(p) + (i << 23));
}

#define CP16(dst, src) asm volatile("cp.async.ca.shared.global [%0],[%1],16;\n" :: "r"(dst), "l"(src))
#define CPCOMMIT()     asm volatile("cp.async.commit_group;\n")
#define CPWAIT0()      asm volatile("cp.async.wait_group 0;\n")

// ---------------- kernel 0: zero accumulator ----------------
__global__ void k_zero() { g_acc = 0.0; }

// ---------------- kernel 1: normalize, pos (fp32), quantize + pack int8 A fragments --
__global__ void __launch_bounds__(256) k_norm_pack(const float* __restrict__ z1,
                                                   const float* __restrict__ z2) {
    const int b  = blockIdx.y;
    const int p0 = blockIdx.x * 32;
    const int tx = threadIdx.x & 31;   // pixel within tile
    const int ty = threadIdx.x >> 5;   // channel group

    __shared__ float s1[128][33];
    __shared__ float red[5][8][32];
    __shared__ float multsm[32];       // 127/max|z1| per pixel

    const float* z1b = z1 + (size_t)b * CDIM * NPIX + p0;
    const float* z2b = z2 + (size_t)b * CDIM * NPIX + p0;

    float ss1 = 0.f, ss2 = 0.f, dt = 0.f, mm1 = 0.f, mm2 = 0.f;
#pragma unroll
    for (int j = 0; j < 16; j++) {
        int c = ty * 16 + j;
        float v1 = z1b[(size_t)c * NPIX + tx];
        float v2 = z2b[(size_t)c * NPIX + tx];
        ss1 = fmaf(v1, v1, ss1);
        ss2 = fmaf(v2, v2, ss2);
        dt  = fmaf(v1, v2, dt);
        mm1 = fmaxf(mm1, fabsf(v1));
        mm2 = fmaxf(mm2, fabsf(v2));
        s1[c][tx] = v1;
    }
    red[0][ty][tx] = ss1; red[1][ty][tx] = ss2; red[2][ty][tx] = dt;
    red[3][ty][tx] = mm1; red[4][ty][tx] = mm2;
    __syncthreads();

    if (ty == 0) {
        float a = 0.f, bb = 0.f, d = 0.f, m1 = 0.f, m2 = 0.f;
#pragma unroll
        for (int j = 0; j < 8; j++) {
            a += red[0][j][tx]; bb += red[1][j][tx]; d += red[2][j][tx];
            m1 = fmaxf(m1, red[3][j][tx]); m2 = fmaxf(m2, red[4][j][tx]);
        }
        m1 = fmaxf(m1, 1e-20f); m2 = fmaxf(m2, 1e-20f);
        float inv1 = 1.f / fmaxf(sqrtf(a),  1e-12f);
        float inv2 = 1.f / fmaxf(sqrtf(bb), 1e-12f);
        int pix = b * NPIX + p0 + tx;
        multsm[tx]   = 127.f / m1;
        g_ra  [pix]  = m1 * inv1 * (1.f / 127.f);
        g_rb  [pix]  = SCALE_L2 * m2 * inv2 * (1.f / 127.f);
        g_qb2 [pix]  = 127.f / m2;
        g_posl2[pix] = d * inv1 * inv2 * SCALE_L2;  // pos in log2 domain (fp32 exact)
    }
    __syncthreads();

    // Pack A into int8 m16n8k32 fragment order.
    {
        int i    = threadIdx.x;
        int rbl  = i >> 7;                 // 0..1 local rowblock of 16 rows
        int rem  = i & 127;
        int s    = rem >> 5;               // kstep 0..3 (K=32 each)
        int lane = rem & 31;
        int gid  = lane >> 2, tig = lane & 3;
        int pl   = rbl * 16 + gid;
        int kb   = s * 32 + tig * 4;
        float q1 = multsm[pl], q2 = multsm[pl + 8];
        uint4 o;
        o.x = pk4i(s1[kb   ][pl    ] * q1, s1[kb + 1][pl    ] * q1, s1[kb + 2][pl    ] * q1, s1[kb + 3][pl    ] * q1);
        o.y = pk4i(s1[kb   ][pl + 8] * q2, s1[kb + 1][pl + 8] * q2, s1[kb + 2][pl + 8] * q2, s1[kb + 3][pl + 8] * q2);
        o.z = pk4i(s1[kb+16][pl    ] * q1, s1[kb +17][pl    ] * q1, s1[kb +18][pl    ] * q1, s1[kb +19][pl    ] * q1);
        o.w = pk4i(s1[kb+16][pl + 8] * q2, s1[kb +17][pl + 8] * q2, s1[kb +18][pl + 8] * q2, s1[kb +19][pl + 8] * q2);
        int rb = blockIdx.x * 2 + rbl;
        g_Apack[((b * NROWBLK + rb) * 4 + s) * 32 + lane] = o;
    }
}

// ---------------- kernel 2: pack int8 B fragments (last chunk of z2) --------
// uint4 entry [b][it][(nb*2+s2)*32+lane]: .xy = {b0,b1} for s=2*s2, .zw = s=2*s2+1
// 16384 entries total: b(1) | it(4) | pair(4) | lane(5) = 13 bits per batch.
__global__ void __launch_bounds__(256) k_packB(const float* __restrict__ z2) {
    int g = blockIdx.x * 256 + threadIdx.x;       // 0..16383
    int b    = g >> 13;
    int r    = g & 8191;
    int it   = r >> 9;                            // 0..15
    int idx  = r & 511;
    int pair = idx >> 5;                          // nb*2+s2, 0..15
    int lane = idx & 31;
    int nb = pair >> 1, s2 = pair & 1;
    int gid = lane >> 2, tig = lane & 3;
    int col = it * 64 + nb * 8 + gid;             // 0..1023
    int pq  = LAST0 + col;
    float qm = g_qb2[b * NPIX + pq];              // 127/max|z2_raw|
    const float* zp = z2 + (size_t)b * CDIM * NPIX + pq;
    uint4 o;
#pragma unroll
    for (int h = 0; h < 2; h++) {
        int s  = 2 * s2 + h;
        int k0 = s * 32 + tig * 4;
        unsigned lo = pk4i(zp[(size_t)(k0     ) * NPIX] * qm, zp[(size_t)(k0 +  1) * NPIX] * qm,
                           zp[(size_t)(k0 +  2) * NPIX] * qm, zp[(size_t)(k0 +  3) * NPIX] * qm);
        unsigned hi = pk4i(zp[(size_t)(k0 + 16) * NPIX] * qm, zp[(size_t)(k0 + 17) * NPIX] * qm,
                           zp[(size_t)(k0 + 18) * NPIX] * qm, zp[(size_t)(k0 + 19) * NPIX] * qm);
        if (h == 0) { o.x = lo; o.y = hi; } else { o.z = lo; o.w = hi; }
    }
    g_Bpack[g] = o;
}

// ---------------- kernel 3: int8 GEMM (mma.sync m16n8k32) + fused epilogue ----------
__global__ void __launch_bounds__(256, 3) k_main(const int* __restrict__ labels) {
    const int b    = blockIdx.y;
    const int row0 = blockIdx.x * 128;
    const int tid  = threadIdx.x;
    const int w    = tid >> 5;
    const int lane = tid & 31;
    const int gid  = lane >> 2, tig = lane & 3;

    __shared__ uint4 Bsm[2][512];    // double-buffered 8KB int8 tiles (64 cols x 128 K)
    __shared__ int   labrb[2048];    // interleaved {label, rb_bits} per col
    __shared__ float warpsum[8];

    // build col table: label + dequant scale
    for (int i = tid; i < 1024; i += 256) {
        labrb[2 * i]     = labels[b * NPIX + LAST0 + i];
        labrb[2 * i + 1] = __float_as_int(g_rb[b * NPIX + LAST0 + i]);
    }

    // A fragments for this warp's 16 rows: 4 x uint4 = 16 regs
    const int rb = blockIdx.x * 8 + w;
    uint4 a[4];
    const uint4* Ap = g_Apack + ((size_t)(b * NROWBLK + rb) * 4) * 32 + lane;
#pragma unroll
    for (int s = 0; s < 4; s++) a[s] = Ap[s * 32];

    const int r0  = row0 + w * 16 + gid;
    const int lr0 = labels[b * NPIX + r0];
    const int lr1 = labels[b * NPIX + r0 + 8];
    const u64 RA0 = bc(g_ra[b * NPIX + r0]);
    const u64 RA1 = bc(g_ra[b * NPIX + r0 + 8]);

    // packed constants
    const u64 MAG  = bc(12582912.0f);   // 1.5 * 2^23
    const u64 NMAG = bc(-12582912.0f);
    const u64 NONE = bc(-1.0f);
    const u64 C5 = bc(1.3333558146e-3f);
    const u64 C4 = bc(9.6181291076e-3f);
    const u64 C3 = bc(5.5504108664e-2f);
    const u64 C2 = bc(2.4022650696e-1f);
    const u64 C1 = bc(6.9314718056e-1f);
    const u64 ONE = bc(1.0f);

    u64 sxp0 = 0, sxp1 = 0, sep0 = 0, sep1 = 0;

    const uint4* Bp = g_Bpack + b * 8192;

    // prefetch tile 0
    {
        unsigned sd = (unsigned)__cvta_generic_to_shared(&Bsm[0][0]);
#pragma unroll
        for (int i = 0; i < 2; i++)
            CP16(sd + (tid + 256 * i) * 16, Bp + tid + 256 * i);
        CPCOMMIT();
    }

    for (int it = 0; it < 16; it++) {
        const int buf = it & 1;
        CPWAIT0();
        __syncthreads();
        if (it < 15) {
            unsigned sd = (unsigned)__cvta_generic_to_shared(&Bsm[buf ^ 1][0]);
            const uint4* src = Bp + (it + 1) * 512;
#pragma unroll
            for (int i = 0; i < 2; i++)
                CP16(sd + (tid + 256 * i) * 16, src + tid + 256 * i);
            CPCOMMIT();
        }

        const uint4* Bb = &Bsm[buf][0];
#pragma unroll
        for (int nb = 0; nb < 8; nb++) {
            int e0 = 0, e1 = 0, e2 = 0, e3 = 0;   // k-steps 0,1
            int o0 = 0, o1 = 0, o2 = 0, o3 = 0;   // k-steps 2,3
            uint4 bf0 = Bb[(nb * 2    ) * 32 + lane];
            uint4 bf1 = Bb[(nb * 2 + 1) * 32 + lane];
            asm volatile(
                "mma.sync.aligned.m16n8k32.row.col.s32.s8.s8.s32 "
                "{%0,%1,%2,%3}, {%4,%5,%6,%7}, {%8,%9}, {%0,%1,%2,%3};\n"
                : "+r"(e0), "+r"(e1), "+r"(e2), "+r"(e3)
                : "r"(a[0].x), "r"(a[0].y), "r"(a[0].z), "r"(a[0].w),
                  "r"(bf0.x), "r"(bf0.y));
            asm volatile(
                "mma.sync.aligned.m16n8k32.row.col.s32.s8.s8.s32 "
                "{%0,%1,%2,%3}, {%4,%5,%6,%7}, {%8,%9}, {%0,%1,%2,%3};\n"
                : "+r"(o0), "+r"(o1), "+r"(o2), "+r"(o3)
                : "r"(a[2].x), "r"(a[2].y), "r"(a[2].z), "r"(a[2].w),
                  "r"(bf1.x), "r"(bf1.y));
            asm volatile(
                "mma.sync.aligned.m16n8k32.row.col.s32.s8.s8.s32 "
                "{%0,%1,%2,%3}, {%4,%5,%6,%7}, {%8,%9}, {%0,%1,%2,%3};\n"
                : "+r"(e0), "+r"(e1), "+r"(e2), "+r"(e3)
                : "r"(a[1].x), "r"(a[1].y), "r"(a[1].z), "r"(a[1].w),
                  "r"(bf0.z), "r"(bf0.w));
            asm volatile(
                "mma.sync.aligned.m16n8k32.row.col.s32.s8.s8.s32 "
                "{%0,%1,%2,%3}, {%4,%5,%6,%7}, {%8,%9}, {%0,%1,%2,%3};\n"
                : "+r"(o0), "+r"(o1), "+r"(o2), "+r"(o3)
                : "r"(a[3].x), "r"(a[3].y), "r"(a[3].z), "r"(a[3].w),
                  "r"(bf1.z), "r"(bf1.w));

            int c0 = e0 + o0, c1 = e1 + o1, c2 = e2 + o2, c3 = e3 + o3;

            // epilogue: mask in int domain, convert, scale (row x col), accumulate
            int4 LR = ((const int4*)labrb)[it * 32 + nb * 4 + tig];  // lab0, rb0, lab1, rb1
            int m0 = (lr0 != LR.x) ? c0 : 0;
            int m1 = (lr0 != LR.z) ? c1 : 0;
            int m2 = (lr1 != LR.x) ? c2 : 0;
            int m3 = (lr1 != LR.z) ? c3 : 0;
            float f0 = (float)m0, f1 = (float)m1, f2 = (float)m2, f3 = (float)m3;
            u64 CS = pk(__int_as_float(LR.y), __int_as_float(LR.w));
            u64 S0 = mul2(CS, RA0);
            u64 S1 = mul2(CS, RA1);
            u64 P0 = mul2(pk(f0, f1), S0);
            u64 P1 = mul2(pk(f2, f3), S1);
            sxp0 = add2(sxp0, P0);
            sxp1 = add2(sxp1, P1);
            {
                u64 t = add2(P0, MAG);
                u64 gg = add2(t, NMAG);
                u64 f = fma2(gg, NONE, P0);
                u64 p = fma2(C5, f, C4);
                p = fma2(p, f, C3); p = fma2(p, f, C2);
                p = fma2(p, f, C1); p = fma2(p, f, ONE);
                unsigned t0, t1, q0, q1;
                asm("mov.b64 {%0,%1},%2;" : "=r"(t0), "=r"(t1) : "l"(t));
                asm("mov.b64 {%0,%1},%2;" : "=r"(q0), "=r"(q1) : "l"(p));
                unsigned r0b = q0 + (t0 << 23), r1b = q1 + (t1 << 23);
                u64 e; asm("mov.b64 %0,{%1,%2};" : "=l"(e) : "r"(r0b), "r"(r1b));
                sep0 = add2(sep0, e);
            }
            {
                u64 t = add2(P1, MAG);
                u64 gg = add2(t, NMAG);
                u64 f = fma2(gg, NONE, P1);
                u64 p = fma2(C5, f, C4);
                p = fma2(p, f, C3); p = fma2(p, f, C2);
                p = fma2(p, f, C1); p = fma2(p, f, ONE);
                unsigned t0, t1, q0, q1;
                asm("mov.b64 {%0,%1},%2;" : "=r"(t0), "=r"(t1) : "l"(t));
                asm("mov.b64 {%0,%1},%2;" : "=r"(q0), "=r"(q1) : "l"(p));
                unsigned r0b = q0 + (t0 << 23), r1b = q1 + (t1 << 23);
                u64 e; asm("mov.b64 %0,{%1,%2};" : "=l"(e) : "r"(r0b), "r"(r1b));
                sep1 = add2(sep1, e);
            }
        }
        __syncthreads();
    }

    // unpack packed accumulators
    float sa, sb;
    asm("mov.b64 {%0,%1},%2;" : "=f"(sa), "=f"(sb) : "l"(sxp0)); float sx0 = sa + sb;
    asm("mov.b64 {%0,%1},%2;" : "=f"(sa), "=f"(sb) : "l"(sep0)); float se0 = sa + sb;
    asm("mov.b64 {%0,%1},%2;" : "=f"(sa), "=f"(sb) : "l"(sxp1)); float sx1 = sa + sb;
    asm("mov.b64 {%0,%1},%2;" : "=f"(sa), "=f"(sb) : "l"(sep1)); float se1 = sa + sb;

    // reduce across the 4 lanes sharing a row
    sx0 += __shfl_xor_sync(~0u, sx0, 1);  sx0 += __shfl_xor_sync(~0u, sx0, 2);
    se0 += __shfl_xor_sync(~0u, se0, 1);  se0 += __shfl_xor_sync(~0u, se0, 2);
    sx1 += __shfl_xor_sync(~0u, sx1, 1);  sx1 += __shfl_xor_sync(~0u, sx1, 2);
    se1 += __shfl_xor_sync(~0u, se1, 1);  se1 += __shfl_xor_sync(~0u, se1, 2);

    float loss = 0.f;
    if (tig == 0) {
        float p0 = g_posl2[b * NPIX + r0];
        float p1 = g_posl2[b * NPIX + r0 + 8];
        float t0 = se0 + exp2p(p0), x0 = sx0 + p0;
        float t1 = se1 + exp2p(p1), x1 = sx1 + p1;
        loss = LN2F * ((__log2f(t0) - x0 * (1.0f / 1025.0f)) +
                       (__log2f(t1) - x1 * (1.0f / 1025.0f)));
    }
#pragma unroll
    for (int o = 16; o; o >>= 1) loss += __shfl_xor_sync(~0u, loss, o);
    if (lane == 0) warpsum[w] = loss;
    __syncthreads();
    if (tid == 0) {
        float t = 0.f;
#pragma unroll
        for (int i = 0; i < 8; i++) t += warpsum[i];
        atomicAdd(&g_acc, (double)t);
    }
}

// ---------------- kernel 4: finalize ----------------
__global__ void k_finalize(float* out) {
    out[0] = (float)(g_acc / (double)(BATCH * NPIX));
}

// ---------------- launch ----------------
extern "C" void kernel_launch(void* const* d_in, const int* in_sizes, int n_in,
                              void* d_out, int out_size) {
    const float* z1     = (const float*)d_in[0];
    const float* z2     = (const float*)d_in[1];
    const int*   labels = (const int*)d_in[2];
    (void)in_sizes; (void)n_in; (void)out_size;

    k_zero<<<1, 1>>>();
    dim3 g1(NPIX / 32, BATCH);
    k_norm_pack<<<g1, 256>>>(z1, z2);
    k_packB<<<64, 256>>>(z2);
    dim3 g2(NPIX / 128, BATCH);
    k_main<<<g2, 256>>>(labels);
    k_finalize<<<1, 1>>>((float*)d_out);
}

// round 7
// speedup vs baseline: 1.9817x; 1.9817x over previous
#include <cuda_runtime.h>
#include <cuda_bf16.h>
#include <cstdint>

// Problem constants (fixed shapes)
#define BATCH 2
#define CDIM 128
#define NPIX 65536          // 256*256
#define LAST0 64512         // (chunks-1)*M
#define NROWBLK 4096        // NPIX/16
#define SCALE_L2 20.6099075f   // 1/(0.07 * ln2)
#define LN2F 0.6931471805599453f

typedef unsigned long long u64;

// ---------------- scratch (device globals: no allocations allowed) ----------
__device__ uint4  g_Apack[BATCH * NROWBLK * 8 * 32];   // 33.5 MB, bf16 mma A fragments
__device__ uint4  g_Bpack[BATCH * 16 * 1024];          // 512 KB: [b][it][(nb*4+s2)*32+lane]
__device__ float  g_inv2[BATCH * NPIX];
__device__ float  g_posl2[BATCH * NPIX];               // pos logit in log2 domain
__device__ double g_acc;

// ---------------- helpers ----------------
__device__ __forceinline__ unsigned pack2(float lo, float hi) {
    __nv_bfloat162 h = __floats2bfloat162_rn(lo, hi);
    return *reinterpret_cast<unsigned*>(&h);
}
__device__ __forceinline__ u64 pk(float lo, float hi) {
    u64 r; asm("mov.b64 %0,{%1,%2};" : "=l"(r) : "f"(lo), "f"(hi)); return r;
}
__device__ __forceinline__ u64 bc(float x) {
    u64 r; asm("mov.b64 %0,{%1,%1};" : "=l"(r) : "f"(x)); return r;
}
__device__ __forceinline__ u64 fma2(u64 a, u64 b, u64 c) {
    u64 d; asm("fma.rn.f32x2 %0,%1,%2,%3;" : "=l"(d) : "l"(a), "l"(b), "l"(c)); return d;
}
__device__ __forceinline__ u64 add2(u64 a, u64 b) {
    u64 d; asm("add.rn.f32x2 %0,%1,%2;" : "=l"(d) : "l"(a), "l"(b)); return d;
}
// scalar exp2 (pos only). Exact at x==0.
__device__ __forceinline__ float exp2p(float x) {
    int   i = __float2int_rn(x);
    float f = x - (float)i;
    float p = 9.6181291076e-3f;
    p = fmaf(p, f, 5.5504108664e-2f);
    p = fmaf(p, f, 2.4022650696e-1f);
    p = fmaf(p, f, 6.9314718056e-1f);
    p = fmaf(p, f, 1.0f);
    return __int_as_float(__float_as_int(p) + (i << 23));
}

#define CP16(dst, src) asm volatile("cp.async.ca.shared.global [%0],[%1],16;\n" :: "r"(dst), "l"(src))
#define CPCOMMIT()     asm volatile("cp.async.commit_group;\n")
#define CPWAIT0()      asm volatile("cp.async.wait_group 0;\n")

#define MMA_BF16(c0, c1, c2, c3, av, b0, b1)                               \
    asm volatile(                                                           \
        "mma.sync.aligned.m16n8k16.row.col.f32.bf16.bf16.f32 "             \
        "{%0,%1,%2,%3}, {%4,%5,%6,%7}, {%8,%9}, {%0,%1,%2,%3};\n"          \
        : "+f"(c0), "+f"(c1), "+f"(c2), "+f"(c3)                            \
        : "r"((av).x), "r"((av).y), "r"((av).z), "r"((av).w),               \
          "r"(b0), "r"(b1))

// packed exp2 accumulate: sep += exp2(P) elementwise (deg-4 Taylor, exact at 0)
#define EXP2ACC(sep, P) do {                                                \
    u64 t  = add2(P, MAG);                                                  \
    u64 gg = add2(t, NMAG);                                                 \
    u64 f  = fma2(gg, NONE, P);                                             \
    u64 p  = fma2(C4, f, C3);                                               \
    p = fma2(p, f, C2); p = fma2(p, f, C1); p = fma2(p, f, ONE);            \
    unsigned t0, t1, q0, q1;                                                \
    asm("mov.b64 {%0,%1},%2;" : "=r"(t0), "=r"(t1) : "l"(t));               \
    asm("mov.b64 {%0,%1},%2;" : "=r"(q0), "=r"(q1) : "l"(p));               \
    q0 += t0 << 23; q1 += t1 << 23;                                         \
    u64 e; asm("mov.b64 %0,{%1,%2};" : "=l"(e) : "r"(q0), "r"(q1));         \
    sep = add2(sep, e);                                                     \
} while (0)

// ---------------- kernel 0: zero accumulator ----------------
__global__ void k_zero() { g_acc = 0.0; }

// ---------------- kernel 1: normalize z1/z2, compute pos (fp32), pack A fragments ----
__global__ void __launch_bounds__(256) k_norm_pack(const float* __restrict__ z1,
                                                   const float* __restrict__ z2) {
    const int b  = blockIdx.y;
    const int p0 = blockIdx.x * 32;
    const int tx = threadIdx.x & 31;   // pixel within tile
    const int ty = threadIdx.x >> 5;   // channel group

    __shared__ float s1[128][33];
    __shared__ float red[3][8][32];
    __shared__ float invsm[32];

    const float* z1b = z1 + (size_t)b * CDIM * NPIX + p0;
    const float* z2b = z2 + (size_t)b * CDIM * NPIX + p0;

    float ss1 = 0.f, ss2 = 0.f, dt = 0.f;
#pragma unroll
    for (int j = 0; j < 16; j++) {
        int c = ty * 16 + j;
        float v1 = z1b[(size_t)c * NPIX + tx];
        float v2 = z2b[(size_t)c * NPIX + tx];
        ss1 = fmaf(v1, v1, ss1);
        ss2 = fmaf(v2, v2, ss2);
        dt  = fmaf(v1, v2, dt);
        s1[c][tx] = v1;
    }
    red[0][ty][tx] = ss1; red[1][ty][tx] = ss2; red[2][ty][tx] = dt;
    __syncthreads();

    if (ty == 0) {
        float a = 0.f, bb = 0.f, d = 0.f;
#pragma unroll
        for (int j = 0; j < 8; j++) { a += red[0][j][tx]; bb += red[1][j][tx]; d += red[2][j][tx]; }
        float inv1 = 1.f / fmaxf(sqrtf(a),  1e-12f);
        float inv2 = 1.f / fmaxf(sqrtf(bb), 1e-12f);
        invsm[tx] = inv1;
        g_inv2 [b * NPIX + p0 + tx] = inv2;
        g_posl2[b * NPIX + p0 + tx] = d * inv1 * inv2 * SCALE_L2;  // pos in log2 domain
    }
    __syncthreads();

    // Pack A into mma fragment order
#pragma unroll
    for (int q = 0; q < 2; q++) {
        int wi   = threadIdx.x + q * 256;
        int rbl  = wi >> 8;
        int rem  = wi & 255;
        int s    = rem >> 5;
        int lane = rem & 31;
        int gid  = lane >> 2, tig = lane & 3;
        int pl   = rbl * 16 + gid;
        int k0   = s * 16 + tig * 2;
        float i1 = invsm[pl], i2 = invsm[pl + 8];
        uint4 o;
        o.x = pack2(s1[k0    ][pl]     * i1, s1[k0 + 1][pl]     * i1);
        o.y = pack2(s1[k0    ][pl + 8] * i2, s1[k0 + 1][pl + 8] * i2);
        o.z = pack2(s1[k0 + 8][pl]     * i1, s1[k0 + 9][pl]     * i1);
        o.w = pack2(s1[k0 + 8][pl + 8] * i2, s1[k0 + 9][pl + 8] * i2);
        int rb = blockIdx.x * 2 + rbl;
        g_Apack[((b * NROWBLK + rb) * 8 + s) * 32 + lane] = o;
    }
}

// ---------------- kernel 2: pack B fragments as uint4 (2 k-steps per entry) --------
// entry [b][it][(nb*4+s2)*32+lane]: .xy = frag for s=2*s2, .zw = frag s=2*s2+1
__global__ void k_packB(const float* __restrict__ z2) {
    int g = blockIdx.x * 256 + threadIdx.x;       // 0..32767
    int b   = g >> 14;
    int r   = g & 16383;
    int it  = r >> 10;
    int idx = r & 1023;
    int nb  = idx >> 7;
    int s2  = (idx >> 5) & 3;
    int lane = idx & 31;
    int gid = lane >> 2, tig = lane & 3;
    int n  = nb * 8 + gid;
    int pq = LAST0 + it * 64 + n;
    float inv = g_inv2[b * NPIX + pq] * SCALE_L2;
    const float* zp = z2 + (size_t)b * CDIM * NPIX + pq;
    int k0 = s2 * 32 + tig * 2;
    uint4 o;
    o.x = pack2(zp[(size_t)(k0     ) * NPIX] * inv, zp[(size_t)(k0 +  1) * NPIX] * inv);
    o.y = pack2(zp[(size_t)(k0 +  8) * NPIX] * inv, zp[(size_t)(k0 +  9) * NPIX] * inv);
    o.z = pack2(zp[(size_t)(k0 + 16) * NPIX] * inv, zp[(size_t)(k0 + 17) * NPIX] * inv);
    o.w = pack2(zp[(size_t)(k0 + 24) * NPIX] * inv, zp[(size_t)(k0 + 25) * NPIX] * inv);
    g_Bpack[g] = o;
}

// ---------------- kernel 3: bf16 GEMM, 32 rows/warp, 4 mma chains + packed epilogue --
__global__ void __launch_bounds__(128, 3) k_main(const int* __restrict__ labels) {
    const int b    = blockIdx.y;
    const int row0 = blockIdx.x * 128;
    const int tid  = threadIdx.x;      // 0..127
    const int w    = tid >> 5;         // 0..3
    const int lane = tid & 31;
    const int gid  = lane >> 2, tig = lane & 3;

    __shared__ uint4 Bsm[2][1024];   // double-buffered 16KB B tiles
    __shared__ int   labsm[1024];
    __shared__ float warpsum[4];

    // labels of last chunk -> shared (vectorized, 128 threads x 2)
    {
        const uint4* lp = (const uint4*)(labels + b * NPIX + LAST0);
        ((uint4*)labsm)[tid]       = lp[tid];
        ((uint4*)labsm)[tid + 128] = lp[tid + 128];
    }

    // A fragments for this warp's 32 rows (2 rowblocks): 16 x uint4
    const int rb0 = blockIdx.x * 8 + w * 2;
    uint4 a0[8], a1[8];
    const uint4* Ap = g_Apack + ((size_t)(b * NROWBLK + rb0) * 8) * 32 + lane;
#pragma unroll
    for (int s = 0; s < 8; s++) { a0[s] = Ap[s * 32]; a1[s] = Ap[256 + s * 32]; }

    const int r0  = row0 + w * 32 + gid;
    const int lr0 = labels[b * NPIX + r0];
    const int lr1 = labels[b * NPIX + r0 + 8];
    const int lr2 = labels[b * NPIX + r0 + 16];
    const int lr3 = labels[b * NPIX + r0 + 24];

    // packed constants
    const u64 MAG  = bc(12582912.0f);   // 1.5 * 2^23
    const u64 NMAG = bc(-12582912.0f);
    const u64 NONE = bc(-1.0f);
    const u64 C4 = bc(9.6181291076e-3f);
    const u64 C3 = bc(5.5504108664e-2f);
    const u64 C2 = bc(2.4022650696e-1f);
    const u64 C1 = bc(6.9314718056e-1f);
    const u64 ONE = bc(1.0f);

    u64 sxp0 = 0, sxp1 = 0, sxp2 = 0, sxp3 = 0;
    u64 sep0 = 0, sep1 = 0, sep2 = 0, sep3 = 0;

    const uint4* Bp = g_Bpack + b * 16384;

    // prefetch tile 0 (1024 uint4 by 128 threads)
    {
        unsigned sd = (unsigned)__cvta_generic_to_shared(&Bsm[0][0]);
#pragma unroll
        for (int i = 0; i < 8; i++)
            CP16(sd + (tid + 128 * i) * 16, Bp + tid + 128 * i);
        CPCOMMIT();
    }

    for (int it = 0; it < 16; it++) {
        const int buf = it & 1;
        CPWAIT0();
        __syncthreads();
        // prefetch next tile into the other buffer (freed by trailing barrier)
        if (it < 15) {
            unsigned sd = (unsigned)__cvta_generic_to_shared(&Bsm[buf ^ 1][0]);
            const uint4* src = Bp + (it + 1) * 1024;
#pragma unroll
            for (int i = 0; i < 8; i++)
                CP16(sd + (tid + 128 * i) * 16, src + tid + 128 * i);
            CPCOMMIT();
        }

        const uint4* Bb = &Bsm[buf][0];
#pragma unroll
        for (int nb = 0; nb < 8; nb++) {
            // 4 independent chains: {even,odd} k-steps x {rowblock0, rowblock1}
            float eA0 = 0.f, eA1 = 0.f, eA2 = 0.f, eA3 = 0.f;
            float oA0 = 0.f, oA1 = 0.f, oA2 = 0.f, oA3 = 0.f;
            float eB0 = 0.f, eB1 = 0.f, eB2 = 0.f, eB3 = 0.f;
            float oB0 = 0.f, oB1 = 0.f, oB2 = 0.f, oB3 = 0.f;
#pragma unroll
            for (int s2 = 0; s2 < 4; s2++) {
                uint4 bf = Bb[(nb * 4 + s2) * 32 + lane];
                MMA_BF16(eA0, eA1, eA2, eA3, a0[2 * s2],     bf.x, bf.y);
                MMA_BF16(eB0, eB1, eB2, eB3, a1[2 * s2],     bf.x, bf.y);
                MMA_BF16(oA0, oA1, oA2, oA3, a0[2 * s2 + 1], bf.z, bf.w);
                MMA_BF16(oB0, oB1, oB2, oB3, a1[2 * s2 + 1], bf.z, bf.w);
            }
            float cA0 = eA0 + oA0, cA1 = eA1 + oA1, cA2 = eA2 + oA2, cA3 = eA3 + oA3;
            float cB0 = eB0 + oB0, cB1 = eB1 + oB1, cB2 = eB2 + oB2, cB3 = eB3 + oB3;

            // epilogue: mask (equal labels -> 0), packed sum_x / sum_exp2
            int2 lc = ((const int2*)labsm)[it * 32 + nb * 4 + tig];
            u64 P0 = pk((lr0 != lc.x) ? cA0 : 0.f, (lr0 != lc.y) ? cA1 : 0.f);
            u64 P1 = pk((lr1 != lc.x) ? cA2 : 0.f, (lr1 != lc.y) ? cA3 : 0.f);
            u64 P2 = pk((lr2 != lc.x) ? cB0 : 0.f, (lr2 != lc.y) ? cB1 : 0.f);
            u64 P3 = pk((lr3 != lc.x) ? cB2 : 0.f, (lr3 != lc.y) ? cB3 : 0.f);
            sxp0 = add2(sxp0, P0);  EXP2ACC(sep0, P0);
            sxp1 = add2(sxp1, P1);  EXP2ACC(sep1, P1);
            sxp2 = add2(sxp2, P2);  EXP2ACC(sep2, P2);
            sxp3 = add2(sxp3, P3);  EXP2ACC(sep3, P3);
        }
        __syncthreads();   // all reads of buf done before next prefetch overwrites
    }

    // unpack packed accumulators
    float sa, sb;
    asm("mov.b64 {%0,%1},%2;" : "=f"(sa), "=f"(sb) : "l"(sxp0)); float sx0 = sa + sb;
    asm("mov.b64 {%0,%1},%2;" : "=f"(sa), "=f"(sb) : "l"(sep0)); float se0 = sa + sb;
    asm("mov.b64 {%0,%1},%2;" : "=f"(sa), "=f"(sb) : "l"(sxp1)); float sx1 = sa + sb;
    asm("mov.b64 {%0,%1},%2;" : "=f"(sa), "=f"(sb) : "l"(sep1)); float se1 = sa + sb;
    asm("mov.b64 {%0,%1},%2;" : "=f"(sa), "=f"(sb) : "l"(sxp2)); float sx2 = sa + sb;
    asm("mov.b64 {%0,%1},%2;" : "=f"(sa), "=f"(sb) : "l"(sep2)); float se2 = sa + sb;
    asm("mov.b64 {%0,%1},%2;" : "=f"(sa), "=f"(sb) : "l"(sxp3)); float sx3 = sa + sb;
    asm("mov.b64 {%0,%1},%2;" : "=f"(sa), "=f"(sb) : "l"(sep3)); float se3 = sa + sb;

    // reduce across the 4 lanes sharing each row (tig dimension)
#pragma unroll
    for (int o = 1; o <= 2; o <<= 1) {
        sx0 += __shfl_xor_sync(~0u, sx0, o);  se0 += __shfl_xor_sync(~0u, se0, o);
        sx1 += __shfl_xor_sync(~0u, sx1, o);  se1 += __shfl_xor_sync(~0u, se1, o);
        sx2 += __shfl_xor_sync(~0u, sx2, o);  se2 += __shfl_xor_sync(~0u, se2, o);
        sx3 += __shfl_xor_sync(~0u, sx3, o);  se3 += __shfl_xor_sync(~0u, se3, o);
    }

    float loss = 0.f;
    if (tig == 0) {
        float p0 = g_posl2[b * NPIX + r0];
        float p1 = g_posl2[b * NPIX + r0 + 8];
        float p2 = g_posl2[b * NPIX + r0 + 16];
        float p3 = g_posl2[b * NPIX + r0 + 24];
        float t0 = se0 + exp2p(p0), x0 = sx0 + p0;
        float t1 = se1 + exp2p(p1), x1 = sx1 + p1;
        float t2 = se2 + exp2p(p2), x2 = sx2 + p2;
        float t3 = se3 + exp2p(p3), x3 = sx3 + p3;
        loss = LN2F * ((__log2f(t0) + __log2f(t1) + __log2f(t2) + __log2f(t3))
                       - (x0 + x1 + x2 + x3) * (1.0f / 1025.0f));
    }
#pragma unroll
    for (int o = 16; o; o >>= 1) loss += __shfl_xor_sync(~0u, loss, o);
    if (lane == 0) warpsum[w] = loss;
    __syncthreads();
    if (tid == 0) {
        float t = warpsum[0] + warpsum[1] + warpsum[2] + warpsum[3];
        atomicAdd(&g_acc, (double)t);
    }
}

// ---------------- kernel 4: finalize ----------------
__global__ void k_finalize(float* out) {
    out[0] = (float)(g_acc / (double)(BATCH * NPIX));
}

// ---------------- launch ----------------
extern "C" void kernel_launch(void* const* d_in, const int* in_sizes, int n_in,
                              void* d_out, int out_size) {
    const float* z1     = (const float*)d_in[0];
    const float* z2     = (const float*)d_in[1];
    const int*   labels = (const int*)d_in[2];
    (void)in_sizes; (void)n_in; (void)out_size;

    k_zero<<<1, 1>>>();
    dim3 g1(NPIX / 32, BATCH);
    k_norm_pack<<<g1, 256>>>(z1, z2);
    k_packB<<<128, 256>>>(z2);
    dim3 g2(NPIX / 128, BATCH);
    k_main<<<g2, 128>>>(labels);
    k_finalize<<<1, 1>>>((float*)d_out);
}

// round 8
// speedup vs baseline: 2.0168x; 1.0177x over previous
#include <cuda_runtime.h>
#include <cuda_bf16.h>
#include <cstdint>

// Problem constants (fixed shapes)
#define BATCH 2
#define CDIM 128
#define NPIX 65536          // 256*256
#define LAST0 64512         // (chunks-1)*M
#define NROWBLK 4096        // NPIX/16
#define SCALE_L2 20.6099075f   // 1/(0.07 * ln2)
#define LN2F 0.6931471805599453f

typedef unsigned long long u64;

// ---------------- scratch (device globals: no allocations allowed) ----------
__device__ uint4  g_Apack[BATCH * NROWBLK * 8 * 32];   // 33.5 MB, bf16 mma A fragments
__device__ uint4  g_Bpack[BATCH * 16 * 1024];          // 512 KB: [b][it][(nb*4+s2)*32+lane]
__device__ float  g_inv2[BATCH * NPIX];
__device__ float  g_posl2[BATCH * NPIX];               // pos logit in log2 domain
__device__ double g_acc;

// ---------------- helpers ----------------
__device__ __forceinline__ unsigned pack2(float lo, float hi) {
    __nv_bfloat162 h = __floats2bfloat162_rn(lo, hi);
    return *reinterpret_cast<unsigned*>(&h);
}
__device__ __forceinline__ u64 pk(float lo, float hi) {
    u64 r; asm("mov.b64 %0,{%1,%2};" : "=l"(r) : "f"(lo), "f"(hi)); return r;
}
__device__ __forceinline__ u64 bc(float x) {
    u64 r; asm("mov.b64 %0,{%1,%1};" : "=l"(r) : "f"(x)); return r;
}
__device__ __forceinline__ u64 fma2(u64 a, u64 b, u64 c) {
    u64 d; asm("fma.rn.f32x2 %0,%1,%2,%3;" : "=l"(d) : "l"(a), "l"(b), "l"(c)); return d;
}
__device__ __forceinline__ u64 add2(u64 a, u64 b) {
    u64 d; asm("add.rn.f32x2 %0,%1,%2;" : "=l"(d) : "l"(a), "l"(b)); return d;
}
__device__ __forceinline__ u64 sub2(u64 a, u64 b) {
    u64 d; asm("sub.rn.f32x2 %0,%1,%2;" : "=l"(d) : "l"(a), "l"(b)); return d;
}
// scalar exp2 (pos only). Exact at x==0.
__device__ __forceinline__ float exp2p(float x) {
    int   i = __float2int_rn(x);
    float f = x - (float)i;
    float p = 9.6181291076e-3f;
    p = fmaf(p, f, 5.5504108664e-2f);
    p = fmaf(p, f, 2.4022650696e-1f);
    p = fmaf(p, f, 6.9314718056e-1f);
    p = fmaf(p, f, 1.0f);
    return __int_as_float(__float_as_int(p) + (i << 23));
}

#define CP16(dst, src) asm volatile("cp.async.ca.shared.global [%0],[%1],16;\n" :: "r"(dst), "l"(src))
#define CPCOMMIT()     asm volatile("cp.async.commit_group;\n")
#define CPWAIT0()      asm volatile("cp.async.wait_group 0;\n")

#define MMA_BF16(c0, c1, c2, c3, av, b0, b1)                               \
    asm volatile(                                                           \
        "mma.sync.aligned.m16n8k16.row.col.f32.bf16.bf16.f32 "             \
        "{%0,%1,%2,%3}, {%4,%5,%6,%7}, {%8,%9}, {%0,%1,%2,%3};\n"          \
        : "+f"(c0), "+f"(c1), "+f"(c2), "+f"(c3)                            \
        : "r"((av).x), "r"((av).y), "r"((av).z), "r"((av).w),               \
          "r"(b0), "r"(b1))

// packed exp2 accumulate: sep += exp2(P) elementwise (deg-3 Taylor, exact at 0)
#define EXP2ACC(sep, P) do {                                                \
    u64 t  = add2(P, MAG);                                                  \
    u64 ii = sub2(t, MAG);                                                  \
    u64 f  = sub2(P, ii);                                                   \
    u64 p  = fma2(C3, f, C2);                                               \
    p = fma2(p, f, C1); p = fma2(p, f, ONE);                                \
    unsigned t0, t1, q0, q1;                                                \
    asm("mov.b64 {%0,%1},%2;" : "=r"(t0), "=r"(t1) : "l"(t));               \
    asm("mov.b64 {%0,%1},%2;" : "=r"(q0), "=r"(q1) : "l"(p));               \
    q0 += t0 << 23; q1 += t1 << 23;                                         \
    u64 e; asm("mov.b64 %0,{%1,%2};" : "=l"(e) : "r"(q0), "r"(q1));         \
    sep = add2(sep, e);                                                     \
} while (0)

// epilogue on saved (already merged) results c[8] with label pair lcp
#define EPILOGUE(c, lcp) do {                                               \
    u64 P0 = pk((lr0 != (lcp).x) ? (c)[0] : 0.f, (lr0 != (lcp).y) ? (c)[1] : 0.f); \
    u64 P1 = pk((lr1 != (lcp).x) ? (c)[2] : 0.f, (lr1 != (lcp).y) ? (c)[3] : 0.f); \
    u64 P2 = pk((lr2 != (lcp).x) ? (c)[4] : 0.f, (lr2 != (lcp).y) ? (c)[5] : 0.f); \
    u64 P3 = pk((lr3 != (lcp).x) ? (c)[6] : 0.f, (lr3 != (lcp).y) ? (c)[7] : 0.f); \
    sxp = add2(sxp, add2(add2(P0, P1), add2(P2, P3)));                      \
    EXP2ACC(sep0, P0);                                                      \
    EXP2ACC(sep1, P1);                                                      \
    EXP2ACC(sep2, P2);                                                      \
    EXP2ACC(sep3, P3);                                                      \
} while (0)

// ---------------- kernel 0: zero accumulator ----------------
__global__ void k_zero() { g_acc = 0.0; }

// ---------------- kernel 1: normalize z1/z2, compute pos (fp32), pack A fragments ----
__global__ void __launch_bounds__(256) k_norm_pack(const float* __restrict__ z1,
                                                   const float* __restrict__ z2) {
    const int b  = blockIdx.y;
    const int p0 = blockIdx.x * 32;
    const int tx = threadIdx.x & 31;   // pixel within tile
    const int ty = threadIdx.x >> 5;   // channel group

    __shared__ float s1[128][33];
    __shared__ float red[3][8][32];
    __shared__ float invsm[32];

    const float* z1b = z1 + (size_t)b * CDIM * NPIX + p0;
    const float* z2b = z2 + (size_t)b * CDIM * NPIX + p0;

    float ss1 = 0.f, ss2 = 0.f, dt = 0.f;
#pragma unroll
    for (int j = 0; j < 16; j++) {
        int c = ty * 16 + j;
        float v1 = z1b[(size_t)c * NPIX + tx];
        float v2 = z2b[(size_t)c * NPIX + tx];
        ss1 = fmaf(v1, v1, ss1);
        ss2 = fmaf(v2, v2, ss2);
        dt  = fmaf(v1, v2, dt);
        s1[c][tx] = v1;
    }
    red[0][ty][tx] = ss1; red[1][ty][tx] = ss2; red[2][ty][tx] = dt;
    __syncthreads();

    if (ty == 0) {
        float a = 0.f, bb = 0.f, d = 0.f;
#pragma unroll
        for (int j = 0; j < 8; j++) { a += red[0][j][tx]; bb += red[1][j][tx]; d += red[2][j][tx]; }
        float inv1 = 1.f / fmaxf(sqrtf(a),  1e-12f);
        float inv2 = 1.f / fmaxf(sqrtf(bb), 1e-12f);
        invsm[tx] = inv1;
        g_inv2 [b * NPIX + p0 + tx] = inv2;
        g_posl2[b * NPIX + p0 + tx] = d * inv1 * inv2 * SCALE_L2;  // pos in log2 domain
    }
    __syncthreads();

    // Pack A into mma fragment order
#pragma unroll
    for (int q = 0; q < 2; q++) {
        int wi   = threadIdx.x + q * 256;
        int rbl  = wi >> 8;
        int rem  = wi & 255;
        int s    = rem >> 5;
        int lane = rem & 31;
        int gid  = lane >> 2, tig = lane & 3;
        int pl   = rbl * 16 + gid;
        int k0   = s * 16 + tig * 2;
        float i1 = invsm[pl], i2 = invsm[pl + 8];
        uint4 o;
        o.x = pack2(s1[k0    ][pl]     * i1, s1[k0 + 1][pl]     * i1);
        o.y = pack2(s1[k0    ][pl + 8] * i2, s1[k0 + 1][pl + 8] * i2);
        o.z = pack2(s1[k0 + 8][pl]     * i1, s1[k0 + 9][pl]     * i1);
        o.w = pack2(s1[k0 + 8][pl + 8] * i2, s1[k0 + 9][pl + 8] * i2);
        int rb = blockIdx.x * 2 + rbl;
        g_Apack[((b * NROWBLK + rb) * 8 + s) * 32 + lane] = o;
    }
}

// ---------------- kernel 2: pack B fragments as uint4 (2 k-steps per entry) --------
__global__ void k_packB(const float* __restrict__ z2) {
    int g = blockIdx.x * 256 + threadIdx.x;       // 0..32767
    int b   = g >> 14;
    int r   = g & 16383;
    int it  = r >> 10;
    int idx = r & 1023;
    int nb  = idx >> 7;
    int s2  = (idx >> 5) & 3;
    int lane = idx & 31;
    int gid = lane >> 2, tig = lane & 3;
    int n  = nb * 8 + gid;
    int pq = LAST0 + it * 64 + n;
    float inv = g_inv2[b * NPIX + pq] * SCALE_L2;
    const float* zp = z2 + (size_t)b * CDIM * NPIX + pq;
    int k0 = s2 * 32 + tig * 2;
    uint4 o;
    o.x = pack2(zp[(size_t)(k0     ) * NPIX] * inv, zp[(size_t)(k0 +  1) * NPIX] * inv);
    o.y = pack2(zp[(size_t)(k0 +  8) * NPIX] * inv, zp[(size_t)(k0 +  9) * NPIX] * inv);
    o.z = pack2(zp[(size_t)(k0 + 16) * NPIX] * inv, zp[(size_t)(k0 + 17) * NPIX] * inv);
    o.w = pack2(zp[(size_t)(k0 + 24) * NPIX] * inv, zp[(size_t)(k0 + 25) * NPIX] * inv);
    g_Bpack[g] = o;
}

// ---------------- kernel 3: bf16 GEMM, 32 rows/warp, epilogue pipelined by one nb ---
__global__ void __launch_bounds__(128, 3) k_main(const int* __restrict__ labels) {
    const int b    = blockIdx.y;
    const int row0 = blockIdx.x * 128;
    const int tid  = threadIdx.x;      // 0..127
    const int w    = tid >> 5;         // 0..3
    const int lane = tid & 31;
    const int gid  = lane >> 2, tig = lane & 3;

    __shared__ uint4 Bsm[2][1024];   // double-buffered 16KB B tiles
    __shared__ int   labsm[1024];
    __shared__ float warpsum[4];

    // labels of last chunk -> shared (vectorized, 128 threads x 2)
    {
        const uint4* lp = (const uint4*)(labels + b * NPIX + LAST0);
        ((uint4*)labsm)[tid]       = lp[tid];
        ((uint4*)labsm)[tid + 128] = lp[tid + 128];
    }

    // A fragments for this warp's 32 rows (2 rowblocks): 16 x uint4
    const int rb0 = blockIdx.x * 8 + w * 2;
    uint4 a0[8], a1[8];
    const uint4* Ap = g_Apack + ((size_t)(b * NROWBLK + rb0) * 8) * 32 + lane;
#pragma unroll
    for (int s = 0; s < 8; s++) { a0[s] = Ap[s * 32]; a1[s] = Ap[256 + s * 32]; }

    const int r0  = row0 + w * 32 + gid;
    const int lr0 = labels[b * NPIX + r0];
    const int lr1 = labels[b * NPIX + r0 + 8];
    const int lr2 = labels[b * NPIX + r0 + 16];
    const int lr3 = labels[b * NPIX + r0 + 24];

    // packed constants
    const u64 MAG = bc(12582912.0f);   // 1.5 * 2^23
    const u64 C3 = bc(5.5504108664e-2f);
    const u64 C2 = bc(2.4022650696e-1f);
    const u64 C1 = bc(6.9314718056e-1f);
    const u64 ONE = bc(1.0f);

    u64 sxp = 0;                                   // warp-global sum of masked logits
    u64 sep0 = 0, sep1 = 0, sep2 = 0, sep3 = 0;    // per-row-pair exp sums

    // mma chain accumulators + pipelined saved results
    float eA0=0.f,eA1=0.f,eA2=0.f,eA3=0.f, oA0=0.f,oA1=0.f,oA2=0.f,oA3=0.f;
    float eB0=0.f,eB1=0.f,eB2=0.f,eB3=0.f, oB0=0.f,oB1=0.f,oB2=0.f,oB3=0.f;
    float csv[8];
    int2  lcp = make_int2(0, 0);

    const uint4* Bp = g_Bpack + b * 16384;

    // prefetch tile 0 (1024 uint4 by 128 threads)
    {
        unsigned sd = (unsigned)__cvta_generic_to_shared(&Bsm[0][0]);
#pragma unroll
        for (int i = 0; i < 8; i++)
            CP16(sd + (tid + 128 * i) * 16, Bp + tid + 128 * i);
        CPCOMMIT();
    }

    for (int it = 0; it < 16; it++) {
        const int buf = it & 1;
        CPWAIT0();
        __syncthreads();
        // prefetch next tile into the other buffer
        if (it < 15) {
            unsigned sd = (unsigned)__cvta_generic_to_shared(&Bsm[buf ^ 1][0]);
            const uint4* src = Bp + (it + 1) * 1024;
#pragma unroll
            for (int i = 0; i < 8; i++)
                CP16(sd + (tid + 128 * i) * 16, src + tid + 128 * i);
            CPCOMMIT();
        }

        const uint4* Bb = &Bsm[buf][0];
#pragma unroll
        for (int nb = 0; nb < 8; nb++) {
            // (1) merge previous nb's chains into saved regs (results long ready)
            if (it + nb > 0) {
                csv[0] = eA0 + oA0; csv[1] = eA1 + oA1;
                csv[2] = eA2 + oA2; csv[3] = eA3 + oA3;
                csv[4] = eB0 + oB0; csv[5] = eB1 + oB1;
                csv[6] = eB2 + oB2; csv[7] = eB3 + oB3;
            }
            // (2) issue this nb's 16 mmas into the freed chains
            eA0=0.f;eA1=0.f;eA2=0.f;eA3=0.f; oA0=0.f;oA1=0.f;oA2=0.f;oA3=0.f;
            eB0=0.f;eB1=0.f;eB2=0.f;eB3=0.f; oB0=0.f;oB1=0.f;oB2=0.f;oB3=0.f;
#pragma unroll
            for (int s2 = 0; s2 < 4; s2++) {
                uint4 bf = Bb[(nb * 4 + s2) * 32 + lane];
                MMA_BF16(eA0, eA1, eA2, eA3, a0[2 * s2],     bf.x, bf.y);
                MMA_BF16(eB0, eB1, eB2, eB3, a1[2 * s2],     bf.x, bf.y);
                MMA_BF16(oA0, oA1, oA2, oA3, a0[2 * s2 + 1], bf.z, bf.w);
                MMA_BF16(oB0, oB1, oB2, oB3, a1[2 * s2 + 1], bf.z, bf.w);
            }
            // (3) epilogue for the previous nb while these mmas are in flight
            if (it + nb > 0) EPILOGUE(csv, lcp);
            // (4) capture this nb's column labels for next round
            lcp = ((const int2*)labsm)[it * 32 + nb * 4 + tig];
        }
        __syncthreads();   // all reads of buf done before next prefetch overwrites
    }

    // drain: merge + epilogue for the final nb
    csv[0] = eA0 + oA0; csv[1] = eA1 + oA1;
    csv[2] = eA2 + oA2; csv[3] = eA3 + oA3;
    csv[4] = eB0 + oB0; csv[5] = eB1 + oB1;
    csv[6] = eB2 + oB2; csv[7] = eB3 + oB3;
    EPILOGUE(csv, lcp);

    // unpack packed accumulators
    float sa, sb;
    asm("mov.b64 {%0,%1},%2;" : "=f"(sa), "=f"(sb) : "l"(sxp));  float sxw = sa + sb;
    asm("mov.b64 {%0,%1},%2;" : "=f"(sa), "=f"(sb) : "l"(sep0)); float se0 = sa + sb;
    asm("mov.b64 {%0,%1},%2;" : "=f"(sa), "=f"(sb) : "l"(sep1)); float se1 = sa + sb;
    asm("mov.b64 {%0,%1},%2;" : "=f"(sa), "=f"(sb) : "l"(sep2)); float se2 = sa + sb;
    asm("mov.b64 {%0,%1},%2;" : "=f"(sa), "=f"(sb) : "l"(sep3)); float se3 = sa + sb;

    // per-row exp sums: reduce across the 4 lanes sharing each row (tig dimension)
#pragma unroll
    for (int o = 1; o <= 2; o <<= 1) {
        se0 += __shfl_xor_sync(~0u, se0, o);
        se1 += __shfl_xor_sync(~0u, se1, o);
        se2 += __shfl_xor_sync(~0u, se2, o);
        se3 += __shfl_xor_sync(~0u, se3, o);
    }

    // per-lane partial loss: tig==0 lanes own the 4 rows' log terms + pos adjustments
    float v = 0.f;
    if (tig == 0) {
        float p0 = g_posl2[b * NPIX + r0];
        float p1 = g_posl2[b * NPIX + r0 + 8];
        float p2 = g_posl2[b * NPIX + r0 + 16];
        float p3 = g_posl2[b * NPIX + r0 + 24];
        float t0 = se0 + exp2p(p0);
        float t1 = se1 + exp2p(p1);
        float t2 = se2 + exp2p(p2);
        float t3 = se3 + exp2p(p3);
        v = (__log2f(t0) + __log2f(t1) + __log2f(t2) + __log2f(t3))
            - (p0 + p1 + p2 + p3) * (1.0f / 1025.0f);
    }
    v -= sxw * (1.0f / 1025.0f / 32.0f);   // spread warp-global sx over 32 lanes
#pragma unroll
    for (int o = 16; o; o >>= 1) v += __shfl_xor_sync(~0u, v, o);
    float loss = LN2F * v;
    if (lane == 0) warpsum[w] = loss;
    __syncthreads();
    if (tid == 0) {
        float t = warpsum[0] + warpsum[1] + warpsum[2] + warpsum[3];
        atomicAdd(&g_acc, (double)t);
    }
}

// ---------------- kernel 4: finalize ----------------
__global__ void k_finalize(float* out) {
    out[0] = (float)(g_acc / (double)(BATCH * NPIX));
}

// ---------------- launch ----------------
extern "C" void kernel_launch(void* const* d_in, const int* in_sizes, int n_in,
                              void* d_out, int out_size) {
    const float* z1     = (const float*)d_in[0];
    const float* z2     = (const float*)d_in[1];
    const int*   labels = (const int*)d_in[2];
    (void)in_sizes; (void)n_in; (void)out_size;

    k_zero<<<1, 1>>>();
    dim3 g1(NPIX / 32, BATCH);
    k_norm_pack<<<g1, 256>>>(z1, z2);
    k_packB<<<128, 256>>>(z2);
    dim3 g2(NPIX / 128, BATCH);
    k_main<<<g2, 128>>>(labels);
    k_finalize<<<1, 1>>>((float*)d_out);
}